// round 6
// baseline (speedup 1.0000x reference)
#include <cuda_runtime.h>

// Reference: LATENT_DIM=16, N_PARAMS=2, POLY_ORDER=3
#define NVARS   18
#define NPAIRS  9             // 18 outputs as 9 f32x2 column-pairs
#define NPOLY   1330          // 1 + 18 + 171 + 1140
#define BATCH_N 131072
#define TPB     256
#define RPT     4             // batch rows per thread
#define WROW    10            // weight row padded to 10 u64 (80 B) for 16B align

typedef unsigned long long u64;

__device__ __forceinline__ u64 ffma2(u64 a, u64 b, u64 c) {
    u64 d;
    asm("fma.rn.f32x2 %0, %1, %2, %3;" : "=l"(d) : "l"(a), "l"(b), "l"(c));
    return d;
}
__device__ __forceinline__ u64 fmul2(u64 a, u64 b) {
    u64 d;
    asm("mul.rn.f32x2 %0, %1, %2;" : "=l"(d) : "l"(a), "l"(b));
    return d;
}
__device__ __forceinline__ u64 pack2(float lo, float hi) {
    u64 d;
    asm("mov.b64 %0, {%1, %2};" : "=l"(d) : "f"(lo), "f"(hi));
    return d;
}

// 16-byte broadcast shared load (two column-pair weights)
__device__ __forceinline__ void lds128(const u64* p, u64& w0, u64& w1) {
    asm("ld.shared.v2.u64 {%0, %1}, [%2];"
        : "=l"(w0), "=l"(w1)
        : "l"((u64)__cvta_generic_to_shared(p)));
}
__device__ __forceinline__ u64 lds64(const u64* p) {
    u64 w;
    asm("ld.shared.u64 %0, [%1];"
        : "=l"(w) : "l"((u64)__cvta_generic_to_shared(p)));
    return w;
}

// Load one padded weight row (9 col-pairs) into registers.
__device__ __forceinline__ void load_wrow(const u64* row, u64 wp[NPAIRS]) {
    lds128(row + 0, wp[0], wp[1]);
    lds128(row + 2, wp[2], wp[3]);
    lds128(row + 4, wp[4], wp[5]);
    lds128(row + 6, wp[6], wp[7]);
    wp[8] = lds64(row + 8);
}

__global__ void __launch_bounds__(TPB, 1)
vindy_kernel(const float* __restrict__ z,
             const float* __restrict__ betas,
             const float* __restrict__ big_xi,
             const float* __restrict__ mask,
             float* __restrict__ out)
{
    extern __shared__ __align__(16) u64 Wsh[];  // [NPOLY][WROW] pairs, 106400 B

    const int tid = threadIdx.x;

    // Stage W = big_xi * mask as natural adjacent f32 pairs (no duplication).
    for (int i = tid; i < NPOLY * NPAIRS; i += TPB) {
        const int m = i / NPAIRS, p = i % NPAIRS;
        const int g = m * NVARS + 2 * p;
        Wsh[m * WROW + p] = pack2(big_xi[g] * mask[g], big_xi[g + 1] * mask[g + 1]);
    }

    const int base = (blockIdx.x * TPB + tid) * RPT;  // first of 4 rows

    // x = concat(z, betas) per row, stored as duplicated {x,x} pairs so all
    // theta products stay in dup form (no packing ops in the hot loop).
    // Dynamic indexing -> local memory; latency hidden by 36-deep fma bodies.
    u64 xd[RPT][NVARS];
    #pragma unroll
    for (int r = 0; r < RPT; ++r) {
        const int row = base + r;
        const float4* zp = reinterpret_cast<const float4*>(z + (size_t)row * 16);
        #pragma unroll
        for (int q = 0; q < 4; ++q) {
            const float4 v = zp[q];
            xd[r][q * 4 + 0] = pack2(v.x, v.x);
            xd[r][q * 4 + 1] = pack2(v.y, v.y);
            xd[r][q * 4 + 2] = pack2(v.z, v.z);
            xd[r][q * 4 + 3] = pack2(v.w, v.w);
        }
        const float2 bt = reinterpret_cast<const float2*>(betas)[row];
        xd[r][16] = pack2(bt.x, bt.x);
        xd[r][17] = pack2(bt.y, bt.y);
    }

    __syncthreads();

    // acc[r][p] = (out[r][2p], out[r][2p+1]); init with bias row (theta col 0 = 1)
    u64 acc[RPT][NPAIRS];
    {
        u64 wb[NPAIRS];
        load_wrow(Wsh, wb);
        #pragma unroll
        for (int r = 0; r < RPT; ++r)
            #pragma unroll
            for (int p = 0; p < NPAIRS; ++p) acc[r][p] = wb[p];
    }

    const u64* w = Wsh + WROW;  // rows walked strictly sequentially (lex order)

    #pragma unroll 1
    for (int a = 0; a < NVARS; ++a) {
        u64 xa[RPT];
        #pragma unroll
        for (int r = 0; r < RPT; ++r) xa[r] = xd[r][a];

        {   // degree-1 monomial x_a
            u64 wp[NPAIRS];
            load_wrow(w, wp);  w += WROW;
            #pragma unroll
            for (int r = 0; r < RPT; ++r)
                #pragma unroll
                for (int p = 0; p < NPAIRS; ++p)
                    acc[r][p] = ffma2(xa[r], wp[p], acc[r][p]);
        }

        // jump weight pointer to this a's degree-2 rows: layout is all deg1
        // rows first, then deg2, then deg3 — handled by separate cursors.
        #pragma unroll 1
        for (int b = a; b < NVARS; ++b) { (void)b; }  // placeholder removed below
        break;  // restructured below
    }

    // --- restart with explicit section cursors (deg1/deg2/deg3) ---
    // (The loop above only consumed deg-1 row for a=0; redo cleanly.)
    {
        // reset accumulators
        u64 wb[NPAIRS];
        load_wrow(Wsh, wb);
        #pragma unroll
        for (int r = 0; r < RPT; ++r)
            #pragma unroll
            for (int p = 0; p < NPAIRS; ++p) acc[r][p] = wb[p];
    }
    const u64* w1 = Wsh + 1 * WROW;
    const u64* w2 = Wsh + (1 + NVARS) * WROW;
    const u64* w3 = Wsh + (1 + NVARS + (NVARS * (NVARS + 1)) / 2) * WROW;

    #pragma unroll 1
    for (int a = 0; a < NVARS; ++a) {
        u64 xa[RPT];
        #pragma unroll
        for (int r = 0; r < RPT; ++r) xa[r] = xd[r][a];

        {   // degree-1: x_a
            u64 wp[NPAIRS];
            load_wrow(w1, wp);  w1 += WROW;
            #pragma unroll
            for (int r = 0; r < RPT; ++r)
                #pragma unroll
                for (int p = 0; p < NPAIRS; ++p)
                    acc[r][p] = ffma2(xa[r], wp[p], acc[r][p]);
        }

        #pragma unroll 1
        for (int b = a; b < NVARS; ++b) {
            u64 pab[RPT];
            #pragma unroll
            for (int r = 0; r < RPT; ++r) pab[r] = fmul2(xa[r], xd[r][b]);

            {   // degree-2: x_a x_b
                u64 wp[NPAIRS];
                load_wrow(w2, wp);  w2 += WROW;
                #pragma unroll
                for (int r = 0; r < RPT; ++r)
                    #pragma unroll
                    for (int p = 0; p < NPAIRS; ++p)
                        acc[r][p] = ffma2(pab[r], wp[p], acc[r][p]);
            }

            #pragma unroll 1
            for (int c = b; c < NVARS; ++c) {
                // degree-3: x_a x_b x_c
                u64 wp[NPAIRS];
                load_wrow(w3, wp);  w3 += WROW;
                u64 pabc[RPT];
                #pragma unroll
                for (int r = 0; r < RPT; ++r) pabc[r] = fmul2(pab[r], xd[r][c]);
                #pragma unroll
                for (int r = 0; r < RPT; ++r)
                    #pragma unroll
                    for (int p = 0; p < NPAIRS; ++p)
                        acc[r][p] = ffma2(pabc[r], wp[p], acc[r][p]);
            }
        }
    }

    // Write out [BATCH, 18]: acc pairs are contiguous column pairs.
    #pragma unroll
    for (int r = 0; r < RPT; ++r) {
        u64* orow = reinterpret_cast<u64*>(out + (size_t)(base + r) * NVARS);
        #pragma unroll
        for (int p = 0; p < NPAIRS; ++p) orow[p] = acc[r][p];
    }
}

extern "C" void kernel_launch(void* const* d_in, const int* in_sizes, int n_in,
                              void* d_out, int out_size)
{
    const float* z      = (const float*)d_in[0];
    const float* betas  = (const float*)d_in[1];
    const float* big_xi = (const float*)d_in[2];
    const float* mask   = (const float*)d_in[3];
    float* out = (float*)d_out;

    const int smem = NPOLY * WROW * (int)sizeof(u64);  // 106400 B
    cudaFuncSetAttribute(vindy_kernel,
                         cudaFuncAttributeMaxDynamicSharedMemorySize, smem);

    const int grid = BATCH_N / (RPT * TPB);  // 128 blocks = 1 wave
    vindy_kernel<<<grid, TPB, smem>>>(z, betas, big_xi, mask, out);
}

// round 7
// speedup vs baseline: 1.3067x; 1.3067x over previous
#include <cuda_runtime.h>

// Reference: LATENT_DIM=16, N_PARAMS=2, POLY_ORDER=3
#define NVARS   18
#define NPAIRS  9             // 18 outputs as 9 f32x2 column-pairs
#define NPOLY   1330          // 1 + 18 + 171 + 1140
#define BATCH_N 131072
#define TPB     256
#define RPT     2             // batch rows per thread
#define WROW    10            // weight row padded to 10 u64 (80 B) for 16B align

typedef unsigned long long u64;

__device__ __forceinline__ u64 ffma2(u64 a, u64 b, u64 c) {
    u64 d;
    asm("fma.rn.f32x2 %0, %1, %2, %3;" : "=l"(d) : "l"(a), "l"(b), "l"(c));
    return d;
}
__device__ __forceinline__ u64 pack2(float lo, float hi) {
    u64 d;
    asm("mov.b64 %0, {%1, %2};" : "=l"(d) : "f"(lo), "f"(hi));
    return d;
}
__device__ __forceinline__ u64 dup2(float v) { return pack2(v, v); }

// 16-byte broadcast shared load (two column-pair weights)
__device__ __forceinline__ void lds128(const u64* p, u64& w0, u64& w1) {
    asm("ld.shared.v2.u64 {%0, %1}, [%2];"
        : "=l"(w0), "=l"(w1)
        : "l"((u64)__cvta_generic_to_shared(p)));
}
__device__ __forceinline__ u64 lds64(const u64* p) {
    u64 w;
    asm("ld.shared.u64 %0, [%1];"
        : "=l"(w) : "l"((u64)__cvta_generic_to_shared(p)));
    return w;
}
__device__ __forceinline__ void load_wrow(const u64* row, u64 wp[NPAIRS]) {
    lds128(row + 0, wp[0], wp[1]);
    lds128(row + 2, wp[2], wp[3]);
    lds128(row + 4, wp[4], wp[5]);
    lds128(row + 6, wp[6], wp[7]);
    wp[8] = lds64(row + 8);
}

__global__ void __launch_bounds__(TPB, 2)
vindy_kernel(const float* __restrict__ z,
             const float* __restrict__ betas,
             const float* __restrict__ big_xi,
             const float* __restrict__ mask,
             float* __restrict__ out)
{
    extern __shared__ __align__(16) u64 Wsh[];  // [NPOLY][WROW], 106400 B

    const int tid = threadIdx.x;

    // Stage W = big_xi * mask as natural adjacent column pairs (no lane dup).
    for (int i = tid; i < NPOLY * NPAIRS; i += TPB) {
        const int m = i / NPAIRS, p = i % NPAIRS;
        const int g = m * NVARS + 2 * p;
        Wsh[m * WROW + p] = pack2(big_xi[g] * mask[g], big_xi[g + 1] * mask[g + 1]);
    }

    const int base = (blockIdx.x * TPB + tid) * RPT;  // first of 2 rows

    // x = concat(z, betas) per row, plain f32. Dynamic index -> local mem
    // (tiny: 144 B), latency hidden by the 18-ffma2 bodies + 16 warps/SM.
    float xs[RPT][NVARS];
    #pragma unroll
    for (int r = 0; r < RPT; ++r) {
        const int row = base + r;
        const float4* zp = reinterpret_cast<const float4*>(z + (size_t)row * 16);
        #pragma unroll
        for (int q = 0; q < 4; ++q) {
            const float4 v = zp[q];
            xs[r][q * 4 + 0] = v.x;
            xs[r][q * 4 + 1] = v.y;
            xs[r][q * 4 + 2] = v.z;
            xs[r][q * 4 + 3] = v.w;
        }
        const float2 bt = reinterpret_cast<const float2*>(betas)[row];
        xs[r][16] = bt.x;
        xs[r][17] = bt.y;
    }

    __syncthreads();

    // acc[r][p] = (out[r][2p], out[r][2p+1]); init = bias row (theta col0 = 1)
    u64 acc[RPT][NPAIRS];
    {
        u64 wb[NPAIRS];
        load_wrow(Wsh, wb);
        #pragma unroll
        for (int r = 0; r < RPT; ++r)
            #pragma unroll
            for (int p = 0; p < NPAIRS; ++p) acc[r][p] = wb[p];
    }

    const u64* w1 = Wsh + 1 * WROW;
    const u64* w2 = Wsh + (1 + NVARS) * WROW;
    const u64* w3 = Wsh + (1 + NVARS + (NVARS * (NVARS + 1)) / 2) * WROW;

    #pragma unroll 1
    for (int a = 0; a < NVARS; ++a) {
        float xa[RPT];
        #pragma unroll
        for (int r = 0; r < RPT; ++r) xa[r] = xs[r][a];

        {   // degree-1: x_a
            u64 wp[NPAIRS];
            load_wrow(w1, wp);  w1 += WROW;
            #pragma unroll
            for (int r = 0; r < RPT; ++r) {
                const u64 t = dup2(xa[r]);
                #pragma unroll
                for (int p = 0; p < NPAIRS; ++p)
                    acc[r][p] = ffma2(t, wp[p], acc[r][p]);
            }
        }

        #pragma unroll 1
        for (int b = a; b < NVARS; ++b) {
            float pab[RPT];
            #pragma unroll
            for (int r = 0; r < RPT; ++r) pab[r] = xa[r] * xs[r][b];

            {   // degree-2: x_a x_b
                u64 wp[NPAIRS];
                load_wrow(w2, wp);  w2 += WROW;
                #pragma unroll
                for (int r = 0; r < RPT; ++r) {
                    const u64 t = dup2(pab[r]);
                    #pragma unroll
                    for (int p = 0; p < NPAIRS; ++p)
                        acc[r][p] = ffma2(t, wp[p], acc[r][p]);
                }
            }

            #pragma unroll 1
            for (int c = b; c < NVARS; ++c) {
                // degree-3: x_a x_b x_c
                u64 wp[NPAIRS];
                load_wrow(w3, wp);  w3 += WROW;
                #pragma unroll
                for (int r = 0; r < RPT; ++r) {
                    const u64 t = dup2(pab[r] * xs[r][c]);
                    #pragma unroll
                    for (int p = 0; p < NPAIRS; ++p)
                        acc[r][p] = ffma2(t, wp[p], acc[r][p]);
                }
            }
        }
    }

    // Write out [BATCH, 18]: acc pairs are contiguous column pairs.
    #pragma unroll
    for (int r = 0; r < RPT; ++r) {
        u64* orow = reinterpret_cast<u64*>(out + (size_t)(base + r) * NVARS);
        #pragma unroll
        for (int p = 0; p < NPAIRS; ++p) orow[p] = acc[r][p];
    }
}

extern "C" void kernel_launch(void* const* d_in, const int* in_sizes, int n_in,
                              void* d_out, int out_size)
{
    const float* z      = (const float*)d_in[0];
    const float* betas  = (const float*)d_in[1];
    const float* big_xi = (const float*)d_in[2];
    const float* mask   = (const float*)d_in[3];
    float* out = (float*)d_out;

    const int smem = NPOLY * WROW * (int)sizeof(u64);  // 106400 B per block
    cudaFuncSetAttribute(vindy_kernel,
                         cudaFuncAttributeMaxDynamicSharedMemorySize, smem);

    const int grid = BATCH_N / (RPT * TPB);  // 256 blocks, 2 blocks/SM, 1 wave
    vindy_kernel<<<grid, TPB, smem>>>(z, betas, big_xi, mask, out);
}

// round 12
// speedup vs baseline: 1.3919x; 1.0652x over previous
#include <cuda_runtime.h>
#include <cstdint>

// Reference: LATENT_DIM=16, N_PARAMS=2, POLY_ORDER=3
#define NVARS   18
#define NPAIRS  9
#define BATCH_N 131072
#define TPB     256
#define WROW_B  80            // padded weight row: 10 u64 = 80 bytes

typedef unsigned long long u64;
typedef unsigned int u32;

__device__ __forceinline__ u64 ffma2(u64 a, u64 b, u64 c) {
    u64 d;
    asm("fma.rn.f32x2 %0, %1, %2, %3;" : "=l"(d) : "l"(a), "l"(b), "l"(c));
    return d;
}
__device__ __forceinline__ u64 fadd2(u64 a, u64 b) {
    u64 d;
    asm("add.rn.f32x2 %0, %1, %2;" : "=l"(d) : "l"(a), "l"(b));
    return d;
}
__device__ __forceinline__ u64 pack2(float lo, float hi) {
    u64 d;
    asm("mov.b64 %0, {%1, %2};" : "=l"(d) : "f"(lo), "f"(hi));
    return d;
}
__device__ __forceinline__ u64 dup2(float v) { return pack2(v, v); }

// Weight row load: 4x LDS.128 + 1x LDS.64, u32 shared address + imm offsets.
__device__ __forceinline__ void load_wrow(u32 a, u64 wp[NPAIRS]) {
    asm("ld.shared.v2.u64 {%0, %1}, [%2];"      : "=l"(wp[0]), "=l"(wp[1]) : "r"(a));
    asm("ld.shared.v2.u64 {%0, %1}, [%2+16];"   : "=l"(wp[2]), "=l"(wp[3]) : "r"(a));
    asm("ld.shared.v2.u64 {%0, %1}, [%2+32];"   : "=l"(wp[4]), "=l"(wp[5]) : "r"(a));
    asm("ld.shared.v2.u64 {%0, %1}, [%2+48];"   : "=l"(wp[6]), "=l"(wp[7]) : "r"(a));
    asm("ld.shared.u64 %0, [%1+64];"            : "=l"(wp[8])              : "r"(a));
}

// One split-K half over outer index a in [A0, A1).
//  N1/N2/N3: row counts per degree section; G1/G2/G3: global section row starts.
//  HASBIAS: this half owns the theta-constant column.
//  STORE_DIRECT: plain store (runs first) vs read-modify-write (runs second).
template<int A0, int A1, int N1, int N2, int N3, int G1, int G2, int G3,
         bool HASBIAS, bool STORE_DIRECT>
__global__ void __launch_bounds__(TPB, 4)
vindy_half(const float* __restrict__ z,
           const float* __restrict__ betas,
           const float* __restrict__ big_xi,
           const float* __restrict__ mask,
           float* __restrict__ out)
{
    constexpr int NR = 1 + N1 + N2 + N3;   // local row 0 = bias (or zeros)
    extern __shared__ __align__(16) u64 Wsh[];

    const int tid = threadIdx.x;

    // Stage this half's weight rows (3 contiguous global ranges) + bias slot.
    for (int i = tid; i < NR * NPAIRS; i += TPB) {
        const int l = i / NPAIRS, p = i % NPAIRS;
        int g;
        if (l == 0)                 g = HASBIAS ? 0 : -1;
        else if (l < 1 + N1)        g = G1 + (l - 1);
        else if (l < 1 + N1 + N2)   g = G2 + (l - 1 - N1);
        else                        g = G3 + (l - 1 - N1 - N2);
        u64 v = 0;
        if (g >= 0) {
            const int gg = g * NVARS + 2 * p;
            v = pack2(big_xi[gg] * mask[gg], big_xi[gg + 1] * mask[gg + 1]);
        }
        Wsh[l * (WROW_B / 8) + p] = v;
    }

    const int row = blockIdx.x * TPB + tid;   // one batch row per thread

    // x = concat(z, betas); dynamic indexing -> local mem (72 B), OK.
    float xs[NVARS];
    {
        const float4* zp = reinterpret_cast<const float4*>(z + (size_t)row * 16);
        #pragma unroll
        for (int q = 0; q < 4; ++q) {
            const float4 v = zp[q];
            xs[q * 4 + 0] = v.x;
            xs[q * 4 + 1] = v.y;
            xs[q * 4 + 2] = v.z;
            xs[q * 4 + 3] = v.w;
        }
        const float2 bt = reinterpret_cast<const float2*>(betas)[row];
        xs[16] = bt.x;
        xs[17] = bt.y;
    }

    __syncthreads();

    const u32 sb = (u32)__cvta_generic_to_shared(Wsh);
    u32 c1 = sb + 1 * WROW_B;                  // deg-1 cursor
    u32 c2 = sb + (1 + N1) * WROW_B;           // deg-2 cursor
    u32 c3 = sb + (1 + N1 + N2) * WROW_B;      // deg-3 cursor

    // acc[p] = (out[2p], out[2p+1]); init = bias row (zeros for non-bias half)
    u64 acc[NPAIRS];
    load_wrow(sb, acc);

    #pragma unroll 1
    for (int a = A0; a < A1; ++a) {
        const float xa = xs[a];

        {   // degree-1: x_a
            u64 wp[NPAIRS];
            load_wrow(c1, wp);  c1 += WROW_B;
            const u64 t = dup2(xa);
            #pragma unroll
            for (int p = 0; p < NPAIRS; ++p) acc[p] = ffma2(t, wp[p], acc[p]);
        }

        #pragma unroll 1
        for (int b = a; b < NVARS; ++b) {
            const float pab = xa * xs[b];

            {   // degree-2: x_a x_b
                u64 wp[NPAIRS];
                load_wrow(c2, wp);  c2 += WROW_B;
                const u64 t = dup2(pab);
                #pragma unroll
                for (int p = 0; p < NPAIRS; ++p) acc[p] = ffma2(t, wp[p], acc[p]);
            }

            #pragma unroll 1
            for (int c = b; c < NVARS; ++c) {
                // degree-3: x_a x_b x_c
                u64 wp[NPAIRS];
                load_wrow(c3, wp);  c3 += WROW_B;
                const u64 t = dup2(pab * xs[c]);
                #pragma unroll
                for (int p = 0; p < NPAIRS; ++p) acc[p] = ffma2(t, wp[p], acc[p]);
            }
        }
    }

    // Output: contiguous column pairs. Row stride 72 B => 8-byte aligned.
    u64* orow = reinterpret_cast<u64*>(out + (size_t)row * NVARS);
    if (STORE_DIRECT) {
        #pragma unroll
        for (int p = 0; p < NPAIRS; ++p) orow[p] = acc[p];
    } else {
        // Second launch: accumulate onto the first half's partials.
        #pragma unroll
        for (int p = 0; p < NPAIRS; ++p) orow[p] = fadd2(acc[p], orow[p]);
    }
}

// Section-start math (a = outer monomial index):
//   T2(a) = sum_{i<a}(18-i),  T3(a) = sum_{i<a}(18-i)(19-i)/2
// Split at a=4:  T2(4)=66, T3(4)=580.
// Half B: a in [4,18): N1=14, N2=105, N3=560, G1=5,  G2=19+66=85, G3=190+580=770
// Half A: a in [0,4):  N1=4,  N2=66,  N3=580, G1=1,  G2=19,       G3=190 (+bias)
#define SMEM_B ((1 + 14 + 105 + 560) * WROW_B)   // 54400
#define SMEM_A ((1 + 4 + 66 + 580) * WROW_B)     // 52080

extern "C" void kernel_launch(void* const* d_in, const int* in_sizes, int n_in,
                              void* d_out, int out_size)
{
    const float* z      = (const float*)d_in[0];
    const float* betas  = (const float*)d_in[1];
    const float* big_xi = (const float*)d_in[2];
    const float* mask   = (const float*)d_in[3];
    float* out = (float*)d_out;

    auto kB = vindy_half<4, 18, 14, 105, 560, 5, 85, 770, false, true>;
    auto kA = vindy_half<0, 4, 4, 66, 580, 1, 19, 190, true, false>;

    cudaFuncSetAttribute(kB, cudaFuncAttributeMaxDynamicSharedMemorySize, SMEM_B);
    cudaFuncSetAttribute(kA, cudaFuncAttributeMaxDynamicSharedMemorySize, SMEM_A);

    const int grid = BATCH_N / TPB;   // 512 blocks, 4 blocks/SM -> 1 wave each
    kB<<<grid, TPB, SMEM_B>>>(z, betas, big_xi, mask, out);
    kA<<<grid, TPB, SMEM_A>>>(z, betas, big_xi, mask, out);
}